// round 13
// baseline (speedup 1.0000x reference)
#include <cuda_runtime.h>
#include <math.h>

#define BM 128
#define BN 128
#define BK 32
#define THREADS 256
#define STAGES 3

#define NB    2048
#define LL    64
#define EE    256
#define UU    512
#define MROWS (NB*LL)      // 131072
#define CTX_ELEMS (NB*EE)  // 524288

// smem geometry (floats)
#define AS_STRIDE 36               // 32 + 4 pad, row = 144B (16B-aligned)
#define BS_STRIDE 132              // 128 + 4 pad, row = 528B (16B-aligned)
#define AS_FLOATS (BM * AS_STRIDE) // 4608
#define BS_FLOATS (BK * BS_STRIDE) // 4224
#define STAGE_FLOATS (AS_FLOATS + BS_FLOATS) // 8832
#define SMEM_BYTES (STAGES * STAGE_FLOATS * 4) // 105984

// Scratch (no allocs allowed)
__device__ float g_projh[NB * UU];   // 4 MB
__device__ float g_score[NB * LL];   // 512 KB

__device__ __forceinline__ unsigned f2tf32(float x) {
    unsigned u;
    asm("cvt.rna.tf32.f32 %0, %1;" : "=r"(u) : "f"(x));
    return u;
}

__device__ __forceinline__ unsigned smem_u32(const void* p) {
    return (unsigned)__cvta_generic_to_shared(p);
}

__device__ __forceinline__ void cp_async16(unsigned dst, const void* src) {
    asm volatile("cp.async.cg.shared.global [%0], [%1], 16;\n"
                 :: "r"(dst), "l"(src));
}

// ---------------------------------------------------------------------------
// Tiled tf32 GEMM, 128x128 CTA tile, 8 warps (4M x 2N), warp tile 32x64.
// 3-stage cp.async pipeline, raw fp32 in smem, RNA->tf32 at fragment load.
// MODE 0: proj_h = hidden @ W2 + (b1+b2); also zero-inits g_score.
// MODE 1: fused epilogue score[r] += sum_u V[u]*tanh(acc + proj_h[b,u])
// ---------------------------------------------------------------------------
template <int MODE>
__global__ __launch_bounds__(256)
void gemm_tf32_kernel(const float* __restrict__ A,   // [M, K] row-major
                      const float* __restrict__ Bm,  // [K, 512] row-major
                      int K,
                      const float* __restrict__ b1,
                      const float* __restrict__ b2,
                      const float* __restrict__ Vv)
{
    extern __shared__ float smem[];

    const int tid = threadIdx.x;
    const int m0 = blockIdx.x * BM;
    const int n0 = blockIdx.y * BN;

    if (MODE == 0) {
        // zero score buffer (must happen every graph replay)
        int flat = (blockIdx.y * gridDim.x + blockIdx.x) * THREADS + tid;
        int tot  = gridDim.x * gridDim.y * THREADS;
        for (int i = flat; i < NB * LL; i += tot) g_score[i] = 0.f;
    }

    const int lane = tid & 31, warp = tid >> 5;
    const int gid = lane >> 2, tig = lane & 3;
    const int wm = warp & 3, wn = warp >> 2;  // warp grid 4 (M) x 2 (N)
    const int mw = wm * 32, nw = wn * 64;

    float acc[2][8][4];
    #pragma unroll
    for (int i = 0; i < 2; i++)
        #pragma unroll
        for (int j = 0; j < 8; j++)
            #pragma unroll
            for (int k = 0; k < 4; k++) acc[i][j][k] = 0.f;

    // cooperative-load indices (16B granules)
    const int a_c4 = tid & 7;    // float4 column within BK=32
    const int a_r  = tid >> 3;   // row 0..31, step 32 (x4)
    const int b_c4 = tid & 31;   // float4 column within BN=128
    const int b_r  = tid >> 5;   // row 0..7, step 8 (x4)

    const int nt_k = K >> 5;     // K / BK

    // precomputed smem store addresses per stage
    unsigned aDst[STAGES], bDst[STAGES];
    #pragma unroll
    for (int s = 0; s < STAGES; s++) {
        aDst[s] = smem_u32(smem + s * STAGE_FLOATS + a_r * AS_STRIDE + a_c4 * 4);
        bDst[s] = smem_u32(smem + s * STAGE_FLOATS + AS_FLOATS + b_r * BS_STRIDE + b_c4 * 4);
    }

    const float* Abase = A + (size_t)(m0 + a_r) * K + a_c4 * 4;
    const float* Bbase = Bm + (size_t)b_r * 512 + n0 + b_c4 * 4;

    auto issue_stage = [&](int kt, int s) {
        const float* Ap = Abase + kt * BK;
        #pragma unroll
        for (int i = 0; i < 4; i++)
            cp_async16(aDst[s] + i * 32 * AS_STRIDE * 4, Ap + (size_t)(32 * i) * K);
        const float* Bp = Bbase + (size_t)(kt * BK) * 512;
        #pragma unroll
        for (int i = 0; i < 4; i++)
            cp_async16(bDst[s] + i * 8 * BS_STRIDE * 4, Bp + (size_t)(8 * i) * 512);
        asm volatile("cp.async.commit_group;\n");
    };

    // prologue: stages 0..STAGES-2
    #pragma unroll
    for (int s = 0; s < STAGES - 1; s++) issue_stage(s, s);

    for (int kt = 0; kt < nt_k; kt++) {
        const int sc = kt % STAGES;
        asm volatile("cp.async.wait_group %0;\n" :: "n"(STAGES - 2));
        __syncthreads();

        // refill: buffer (kt-1)%STAGES was fully consumed last iteration
        if (kt + STAGES - 1 < nt_k)
            issue_stage(kt + STAGES - 1, (kt + STAGES - 1) % STAGES);
        else
            asm volatile("cp.async.commit_group;\n");  // empty group keeps counting uniform

        const float* Asp = smem + sc * STAGE_FLOATS;
        const float* Bsp = Asp + AS_FLOATS;

        #pragma unroll
        for (int kk = 0; kk < 4; kk++) {
            unsigned a[2][4];
            #pragma unroll
            for (int mt = 0; mt < 2; mt++) {
                const int r = mw + mt * 16 + gid;
                a[mt][0] = f2tf32(Asp[ r      * AS_STRIDE + kk * 8 + tig]);
                a[mt][1] = f2tf32(Asp[(r + 8) * AS_STRIDE + kk * 8 + tig]);
                a[mt][2] = f2tf32(Asp[ r      * AS_STRIDE + kk * 8 + tig + 4]);
                a[mt][3] = f2tf32(Asp[(r + 8) * AS_STRIDE + kk * 8 + tig + 4]);
            }
            #pragma unroll
            for (int nt = 0; nt < 8; nt++) {
                const int c = nw + nt * 8 + gid;
                unsigned bb0 = f2tf32(Bsp[(kk * 8 + tig    ) * BS_STRIDE + c]);
                unsigned bb1 = f2tf32(Bsp[(kk * 8 + tig + 4) * BS_STRIDE + c]);
                #pragma unroll
                for (int mt = 0; mt < 2; mt++) {
                    asm volatile(
                        "mma.sync.aligned.m16n8k8.row.col.f32.tf32.tf32.f32 "
                        "{%0,%1,%2,%3}, {%4,%5,%6,%7}, {%8,%9}, {%0,%1,%2,%3};\n"
                        : "+f"(acc[mt][nt][0]), "+f"(acc[mt][nt][1]),
                          "+f"(acc[mt][nt][2]), "+f"(acc[mt][nt][3])
                        : "r"(a[mt][0]), "r"(a[mt][1]), "r"(a[mt][2]), "r"(a[mt][3]),
                          "r"(bb0), "r"(bb1));
                }
            }
        }
        // next iteration's __syncthreads guards buffer reuse
    }

    // ------------------------- epilogue -------------------------
    if (MODE == 0) {
        #pragma unroll
        for (int mt = 0; mt < 2; mt++) {
            int r0 = m0 + mw + mt * 16 + gid;
            #pragma unroll
            for (int nt = 0; nt < 8; nt++) {
                int c0 = n0 + nw + nt * 8 + tig * 2;
                float bias0 = b1[c0] + b2[c0];
                float bias1 = b1[c0 + 1] + b2[c0 + 1];
                g_projh[(size_t)r0 * 512 + c0]           = acc[mt][nt][0] + bias0;
                g_projh[(size_t)r0 * 512 + c0 + 1]       = acc[mt][nt][1] + bias1;
                g_projh[(size_t)(r0 + 8) * 512 + c0]     = acc[mt][nt][2] + bias0;
                g_projh[(size_t)(r0 + 8) * 512 + c0 + 1] = acc[mt][nt][3] + bias1;
            }
        }
    } else {
        #pragma unroll
        for (int mt = 0; mt < 2; mt++) {
            int r0 = m0 + mw + mt * 16 + gid;          // rows r0 and r0+8 share batch
            int bidx = r0 >> 6;
            const float* ph = g_projh + (size_t)bidx * 512;
            float p0 = 0.f, p1 = 0.f;
            #pragma unroll
            for (int nt = 0; nt < 8; nt++) {
                int c0 = n0 + nw + nt * 8 + tig * 2;
                float v0 = Vv[c0], v1 = Vv[c0 + 1];
                float h0 = ph[c0], h1 = ph[c0 + 1];
                p0 += v0 * tanhf(acc[mt][nt][0] + h0);
                p0 += v1 * tanhf(acc[mt][nt][1] + h1);
                p1 += v0 * tanhf(acc[mt][nt][2] + h0);
                p1 += v1 * tanhf(acc[mt][nt][3] + h1);
            }
            p0 += __shfl_xor_sync(0xffffffffu, p0, 1);
            p0 += __shfl_xor_sync(0xffffffffu, p0, 2);
            p1 += __shfl_xor_sync(0xffffffffu, p1, 1);
            p1 += __shfl_xor_sync(0xffffffffu, p1, 2);
            if (tig == 0) {
                atomicAdd(&g_score[r0], p0);
                atomicAdd(&g_score[r0 + 8], p1);
            }
        }
    }
}

// ---------------------------------------------------------------------------
// Softmax over L=64 + context = sum_l w[l] * features[b,l,:]
// out layout: [0, 524288) context [2048,256]; [524288, 655360) weights [2048,64]
// ---------------------------------------------------------------------------
__global__ __launch_bounds__(256)
void softmax_ctx_kernel(const float* __restrict__ feat, float* __restrict__ out)
{
    const int b = blockIdx.x;
    const int tid = threadIdx.x;

    __shared__ float w[LL];
    __shared__ float redmax[2];
    __shared__ float redsum[2];

    float s = (tid < LL) ? g_score[b * LL + tid] : -3.0e38f;

    float m = s;
    #pragma unroll
    for (int o = 16; o > 0; o >>= 1)
        m = fmaxf(m, __shfl_xor_sync(0xffffffffu, m, o));
    if (tid == 0)  redmax[0] = m;
    if (tid == 32) redmax[1] = m;
    __syncthreads();
    const float mx = fmaxf(redmax[0], redmax[1]);

    float e = (tid < LL) ? expf(s - mx) : 0.f;
    float sum = e;
    #pragma unroll
    for (int o = 16; o > 0; o >>= 1)
        sum += __shfl_xor_sync(0xffffffffu, sum, o);
    if (tid == 0)  redsum[0] = sum;
    if (tid == 32) redsum[1] = sum;
    __syncthreads();
    const float tot = redsum[0] + redsum[1];

    if (tid < LL) {
        float wt = e / tot;
        w[tid] = wt;
        out[CTX_ELEMS + b * LL + tid] = wt;
    }
    __syncthreads();

    // context: each thread owns one embedding channel (E = 256 = blockDim)
    float acc = 0.f;
    const float* fb = feat + (size_t)b * LL * EE + tid;
    #pragma unroll 16
    for (int l = 0; l < LL; l++)
        acc = fmaf(w[l], fb[l * EE], acc);
    out[b * EE + tid] = acc;
}

// ---------------------------------------------------------------------------
extern "C" void kernel_launch(void* const* d_in, const int* in_sizes, int n_in,
                              void* d_out, int out_size)
{
    const float* features = (const float*)d_in[0];  // [2048,64,256]
    const float* hidden   = (const float*)d_in[1];  // [2048,512]
    const float* W1       = (const float*)d_in[2];  // [256,512]
    const float* b1       = (const float*)d_in[3];  // [512]
    const float* W2       = (const float*)d_in[4];  // [512,512]
    const float* b2       = (const float*)d_in[5];  // [512]
    const float* V        = (const float*)d_in[6];  // [512,1]
    // d_in[7] = bv: constant added to every score -> softmax-invariant, ignored.
    float* out = (float*)d_out;

    // dynamic smem > 48KB requires opt-in (idempotent; immediate host-side call)
    cudaFuncSetAttribute(gemm_tf32_kernel<0>,
                         cudaFuncAttributeMaxDynamicSharedMemorySize, SMEM_BYTES);
    cudaFuncSetAttribute(gemm_tf32_kernel<1>,
                         cudaFuncAttributeMaxDynamicSharedMemorySize, SMEM_BYTES);

    // 1) proj_h = hidden @ W2 + (b1+b2)   [also zero-inits score each replay]
    dim3 g0(NB / BM, UU / BN);       // 16 x 4
    gemm_tf32_kernel<0><<<g0, THREADS, SMEM_BYTES>>>(hidden, W2, UU, b1, b2, nullptr);

    // 2) fused proj_f GEMM + tanh + V-dot -> score (atomic accumulate)
    dim3 g1(MROWS / BM, UU / BN);    // 1024 x 4
    gemm_tf32_kernel<1><<<g1, THREADS, SMEM_BYTES>>>(features, W1, EE, nullptr, nullptr, V);

    // 3) softmax over L + context reduction; writes both outputs
    softmax_ctx_kernel<<<NB, 256>>>(features, out);
}

// round 14
// speedup vs baseline: 1.0008x; 1.0008x over previous
#include <cuda_runtime.h>
#include <math.h>

#define BM 128
#define BN 128
#define BK 32
#define THREADS 256
#define STAGES 3

#define NB    2048
#define LL    64
#define EE    256
#define UU    512
#define MROWS (NB*LL)      // 131072
#define CTX_ELEMS (NB*EE)  // 524288

// smem geometry (floats)
#define AS_STRIDE 36               // 32 + 4 pad, row = 144B (16B-aligned)
#define BS_STRIDE 132              // 128 + 4 pad, row = 528B (16B-aligned)
#define AS_FLOATS (BM * AS_STRIDE) // 4608
#define BS_FLOATS (BK * BS_STRIDE) // 4224
#define STAGE_FLOATS (AS_FLOATS + BS_FLOATS) // 8832
#define SMEM_BYTES (STAGES * STAGE_FLOATS * 4) // 105984

// Scratch (no allocs allowed)
__device__ float g_projh[NB * UU];   // 4 MB
__device__ float g_score[NB * LL];   // 512 KB

__device__ __forceinline__ unsigned f2tf32(float x) {
    unsigned u;
    asm("cvt.rna.tf32.f32 %0, %1;" : "=r"(u) : "f"(x));
    return u;
}

__device__ __forceinline__ unsigned smem_u32(const void* p) {
    return (unsigned)__cvta_generic_to_shared(p);
}

__device__ __forceinline__ void cp_async16(unsigned dst, const void* src) {
    asm volatile("cp.async.cg.shared.global [%0], [%1], 16;\n"
                 :: "r"(dst), "l"(src));
}

// ---------------------------------------------------------------------------
// Tiled tf32 GEMM, 128x128 CTA tile, 8 warps (4M x 2N), warp tile 32x64.
// 3-stage cp.async pipeline, raw fp32 in smem, RNA->tf32 at fragment load.
// MODE 0: proj_h = hidden @ W2 + (b1+b2); also zero-inits g_score.
// MODE 1: fused epilogue score[r] += sum_u V[u]*tanh(acc + proj_h[b,u])
// ---------------------------------------------------------------------------
template <int MODE>
__global__ __launch_bounds__(256)
void gemm_tf32_kernel(const float* __restrict__ A,   // [M, K] row-major
                      const float* __restrict__ Bm,  // [K, 512] row-major
                      int K,
                      const float* __restrict__ b1,
                      const float* __restrict__ b2,
                      const float* __restrict__ Vv)
{
    extern __shared__ float smem[];

    const int tid = threadIdx.x;
    const int m0 = blockIdx.x * BM;
    const int n0 = blockIdx.y * BN;

    if (MODE == 0) {
        // zero score buffer (must happen every graph replay)
        int flat = (blockIdx.y * gridDim.x + blockIdx.x) * THREADS + tid;
        int tot  = gridDim.x * gridDim.y * THREADS;
        for (int i = flat; i < NB * LL; i += tot) g_score[i] = 0.f;
    }

    const int lane = tid & 31, warp = tid >> 5;
    const int gid = lane >> 2, tig = lane & 3;
    const int wm = warp & 3, wn = warp >> 2;  // warp grid 4 (M) x 2 (N)
    const int mw = wm * 32, nw = wn * 64;

    float acc[2][8][4];
    #pragma unroll
    for (int i = 0; i < 2; i++)
        #pragma unroll
        for (int j = 0; j < 8; j++)
            #pragma unroll
            for (int k = 0; k < 4; k++) acc[i][j][k] = 0.f;

    // cooperative-load indices (16B granules)
    const int a_c4 = tid & 7;    // float4 column within BK=32
    const int a_r  = tid >> 3;   // row 0..31, step 32 (x4)
    const int b_c4 = tid & 31;   // float4 column within BN=128
    const int b_r  = tid >> 5;   // row 0..7, step 8 (x4)

    const int nt_k = K >> 5;     // K / BK

    // precomputed smem store addresses per stage
    unsigned aDst[STAGES], bDst[STAGES];
    #pragma unroll
    for (int s = 0; s < STAGES; s++) {
        aDst[s] = smem_u32(smem + s * STAGE_FLOATS + a_r * AS_STRIDE + a_c4 * 4);
        bDst[s] = smem_u32(smem + s * STAGE_FLOATS + AS_FLOATS + b_r * BS_STRIDE + b_c4 * 4);
    }

    const float* Abase = A + (size_t)(m0 + a_r) * K + a_c4 * 4;
    const float* Bbase = Bm + (size_t)b_r * 512 + n0 + b_c4 * 4;

    auto issue_stage = [&](int kt, int s) {
        const float* Ap = Abase + kt * BK;
        #pragma unroll
        for (int i = 0; i < 4; i++)
            cp_async16(aDst[s] + i * 32 * AS_STRIDE * 4, Ap + (size_t)(32 * i) * K);
        const float* Bp = Bbase + (size_t)(kt * BK) * 512;
        #pragma unroll
        for (int i = 0; i < 4; i++)
            cp_async16(bDst[s] + i * 8 * BS_STRIDE * 4, Bp + (size_t)(8 * i) * 512);
        asm volatile("cp.async.commit_group;\n");
    };

    // prologue: stages 0..STAGES-2
    #pragma unroll
    for (int s = 0; s < STAGES - 1; s++) issue_stage(s, s);

    for (int kt = 0; kt < nt_k; kt++) {
        const int sc = kt % STAGES;
        asm volatile("cp.async.wait_group %0;\n" :: "n"(STAGES - 2));
        __syncthreads();

        // refill: buffer (kt-1)%STAGES was fully consumed last iteration
        if (kt + STAGES - 1 < nt_k)
            issue_stage(kt + STAGES - 1, (kt + STAGES - 1) % STAGES);
        else
            asm volatile("cp.async.commit_group;\n");  // empty group keeps counting uniform

        const float* Asp = smem + sc * STAGE_FLOATS;
        const float* Bsp = Asp + AS_FLOATS;

        #pragma unroll
        for (int kk = 0; kk < 4; kk++) {
            unsigned a[2][4];
            #pragma unroll
            for (int mt = 0; mt < 2; mt++) {
                const int r = mw + mt * 16 + gid;
                a[mt][0] = f2tf32(Asp[ r      * AS_STRIDE + kk * 8 + tig]);
                a[mt][1] = f2tf32(Asp[(r + 8) * AS_STRIDE + kk * 8 + tig]);
                a[mt][2] = f2tf32(Asp[ r      * AS_STRIDE + kk * 8 + tig + 4]);
                a[mt][3] = f2tf32(Asp[(r + 8) * AS_STRIDE + kk * 8 + tig + 4]);
            }
            #pragma unroll
            for (int nt = 0; nt < 8; nt++) {
                const int c = nw + nt * 8 + gid;
                unsigned bb0 = f2tf32(Bsp[(kk * 8 + tig    ) * BS_STRIDE + c]);
                unsigned bb1 = f2tf32(Bsp[(kk * 8 + tig + 4) * BS_STRIDE + c]);
                #pragma unroll
                for (int mt = 0; mt < 2; mt++) {
                    asm volatile(
                        "mma.sync.aligned.m16n8k8.row.col.f32.tf32.tf32.f32 "
                        "{%0,%1,%2,%3}, {%4,%5,%6,%7}, {%8,%9}, {%0,%1,%2,%3};\n"
                        : "+f"(acc[mt][nt][0]), "+f"(acc[mt][nt][1]),
                          "+f"(acc[mt][nt][2]), "+f"(acc[mt][nt][3])
                        : "r"(a[mt][0]), "r"(a[mt][1]), "r"(a[mt][2]), "r"(a[mt][3]),
                          "r"(bb0), "r"(bb1));
                }
            }
        }
        // next iteration's __syncthreads guards buffer reuse
    }

    // ------------------------- epilogue -------------------------
    if (MODE == 0) {
        #pragma unroll
        for (int mt = 0; mt < 2; mt++) {
            int r0 = m0 + mw + mt * 16 + gid;
            #pragma unroll
            for (int nt = 0; nt < 8; nt++) {
                int c0 = n0 + nw + nt * 8 + tig * 2;
                float bias0 = b1[c0] + b2[c0];
                float bias1 = b1[c0 + 1] + b2[c0 + 1];
                g_projh[(size_t)r0 * 512 + c0]           = acc[mt][nt][0] + bias0;
                g_projh[(size_t)r0 * 512 + c0 + 1]       = acc[mt][nt][1] + bias1;
                g_projh[(size_t)(r0 + 8) * 512 + c0]     = acc[mt][nt][2] + bias0;
                g_projh[(size_t)(r0 + 8) * 512 + c0 + 1] = acc[mt][nt][3] + bias1;
            }
        }
    } else {
        #pragma unroll
        for (int mt = 0; mt < 2; mt++) {
            int r0 = m0 + mw + mt * 16 + gid;          // rows r0 and r0+8 share batch
            int bidx = r0 >> 6;
            const float* ph = g_projh + (size_t)bidx * 512;
            float p0 = 0.f, p1 = 0.f;
            #pragma unroll
            for (int nt = 0; nt < 8; nt++) {
                int c0 = n0 + nw + nt * 8 + tig * 2;
                float v0 = Vv[c0], v1 = Vv[c0 + 1];
                float h0 = ph[c0], h1 = ph[c0 + 1];
                p0 += v0 * tanhf(acc[mt][nt][0] + h0);
                p0 += v1 * tanhf(acc[mt][nt][1] + h1);
                p1 += v0 * tanhf(acc[mt][nt][2] + h0);
                p1 += v1 * tanhf(acc[mt][nt][3] + h1);
            }
            p0 += __shfl_xor_sync(0xffffffffu, p0, 1);
            p0 += __shfl_xor_sync(0xffffffffu, p0, 2);
            p1 += __shfl_xor_sync(0xffffffffu, p1, 1);
            p1 += __shfl_xor_sync(0xffffffffu, p1, 2);
            if (tig == 0) {
                atomicAdd(&g_score[r0], p0);
                atomicAdd(&g_score[r0 + 8], p1);
            }
        }
    }
}

// ---------------------------------------------------------------------------
// Softmax over L=64 + context = sum_l w[l] * features[b,l,:]
// out layout: [0, 524288) context [2048,256]; [524288, 655360) weights [2048,64]
// ---------------------------------------------------------------------------
__global__ __launch_bounds__(256)
void softmax_ctx_kernel(const float* __restrict__ feat, float* __restrict__ out)
{
    const int b = blockIdx.x;
    const int tid = threadIdx.x;

    __shared__ float w[LL];
    __shared__ float redmax[2];
    __shared__ float redsum[2];

    float s = (tid < LL) ? g_score[b * LL + tid] : -3.0e38f;

    float m = s;
    #pragma unroll
    for (int o = 16; o > 0; o >>= 1)
        m = fmaxf(m, __shfl_xor_sync(0xffffffffu, m, o));
    if (tid == 0)  redmax[0] = m;
    if (tid == 32) redmax[1] = m;
    __syncthreads();
    const float mx = fmaxf(redmax[0], redmax[1]);

    float e = (tid < LL) ? expf(s - mx) : 0.f;
    float sum = e;
    #pragma unroll
    for (int o = 16; o > 0; o >>= 1)
        sum += __shfl_xor_sync(0xffffffffu, sum, o);
    if (tid == 0)  redsum[0] = sum;
    if (tid == 32) redsum[1] = sum;
    __syncthreads();
    const float tot = redsum[0] + redsum[1];

    if (tid < LL) {
        float wt = e / tot;
        w[tid] = wt;
        out[CTX_ELEMS + b * LL + tid] = wt;
    }
    __syncthreads();

    // context: each thread owns one embedding channel (E = 256 = blockDim)
    float acc = 0.f;
    const float* fb = feat + (size_t)b * LL * EE + tid;
    #pragma unroll 16
    for (int l = 0; l < LL; l++)
        acc = fmaf(w[l], fb[l * EE], acc);
    out[b * EE + tid] = acc;
}

// ---------------------------------------------------------------------------
extern "C" void kernel_launch(void* const* d_in, const int* in_sizes, int n_in,
                              void* d_out, int out_size)
{
    const float* features = (const float*)d_in[0];  // [2048,64,256]
    const float* hidden   = (const float*)d_in[1];  // [2048,512]
    const float* W1       = (const float*)d_in[2];  // [256,512]
    const float* b1       = (const float*)d_in[3];  // [512]
    const float* W2       = (const float*)d_in[4];  // [512,512]
    const float* b2       = (const float*)d_in[5];  // [512]
    const float* V        = (const float*)d_in[6];  // [512,1]
    // d_in[7] = bv: constant added to every score -> softmax-invariant, ignored.
    float* out = (float*)d_out;

    // dynamic smem > 48KB requires opt-in (idempotent; immediate host-side call)
    cudaFuncSetAttribute(gemm_tf32_kernel<0>,
                         cudaFuncAttributeMaxDynamicSharedMemorySize, SMEM_BYTES);
    cudaFuncSetAttribute(gemm_tf32_kernel<1>,
                         cudaFuncAttributeMaxDynamicSharedMemorySize, SMEM_BYTES);

    // 1) proj_h = hidden @ W2 + (b1+b2)   [also zero-inits score each replay]
    dim3 g0(NB / BM, UU / BN);       // 16 x 4
    gemm_tf32_kernel<0><<<g0, THREADS, SMEM_BYTES>>>(hidden, W2, UU, b1, b2, nullptr);

    // 2) fused proj_f GEMM + tanh + V-dot -> score (atomic accumulate)
    dim3 g1(MROWS / BM, UU / BN);    // 1024 x 4
    gemm_tf32_kernel<1><<<g1, THREADS, SMEM_BYTES>>>(features, W1, EE, nullptr, nullptr, V);

    // 3) softmax over L + context reduction; writes both outputs
    softmax_ctx_kernel<<<NB, 256>>>(features, out);
}

// round 17
// speedup vs baseline: 1.0573x; 1.0565x over previous
#include <cuda_runtime.h>
#include <math.h>
#include <stdint.h>

#define BM 128
#define BN 128
#define BK 32
#define THREADS 256
#define STAGES 2

#define NB    2048
#define LL    64
#define EE    256
#define UU    512
#define MROWS (NB*LL)      // 131072
#define CTX_ELEMS (NB*EE)  // 524288

// smem geometry (floats)
#define AS_STRIDE 36               // 32 + 4 pad
#define BS_STRIDE 132              // 128 + 4 pad
#define AS_FLOATS (BM * AS_STRIDE) // 4608
#define BS_FLOATS (BK * BS_STRIDE) // 4224
#define STAGE_FLOATS (AS_FLOATS + BS_FLOATS) // 8832
#define SMEM_BYTES (STAGES * STAGE_FLOATS * 4) // 70656 -> 2 CTAs/SM

// Scratch (no allocs allowed)
__device__ float g_projh[NB * UU];   // 4 MB
__device__ float g_score[NB * LL];   // 512 KB
__device__ float g_w1r[EE * UU];     // W1 pre-rounded to tf32 (512 KB)
__device__ float g_w2r[UU * UU];     // W2 pre-rounded to tf32 (1 MB)

__device__ __forceinline__ unsigned f2tf32(float x) {
    unsigned u;
    asm("cvt.rna.tf32.f32 %0, %1;" : "=r"(u) : "f"(x));
    return u;
}
__device__ __forceinline__ unsigned smem_u32(const void* p) {
    return (unsigned)__cvta_generic_to_shared(p);
}
__device__ __forceinline__ void cp_async16(unsigned dst, const void* src) {
    asm volatile("cp.async.cg.shared.global [%0], [%1], 16;\n" :: "r"(dst), "l"(src));
}

// ---------------------------------------------------------------------------
// Pre-round W1 and W2 to tf32 (RNA) once per launch (device-side writes only).
// ---------------------------------------------------------------------------
__global__ __launch_bounds__(256)
void round_weights_kernel(const float* __restrict__ W1, const float* __restrict__ W2)
{
    int idx = blockIdx.x * 256 + threadIdx.x;
    if (idx < EE * UU)
        g_w1r[idx] = __uint_as_float(f2tf32(W1[idx]));
    int idx2 = idx - EE * UU;
    if (idx2 >= 0 && idx2 < UU * UU)
        g_w2r[idx2] = __uint_as_float(f2tf32(W2[idx2]));
}

// ---------------------------------------------------------------------------
// Tiled tf32 GEMM, 128x128 CTA tile, 8 warps (4M x 2N), warp tile 32x64.
// 2-stage cp.async pipeline, 2 CTAs/SM. B (pre-rounded weights) selected
// INSIDE device code from the MODE template — never passed from host.
// MODE 0: proj_h = hidden @ g_w2r + (b1+b2); also zero-inits g_score. K=512.
// MODE 1: fused epilogue score[r] += sum_u V[u]*tanh(acc + proj_h[b,u]). K=256.
// ---------------------------------------------------------------------------
template <int MODE>
__global__ __launch_bounds__(256, 2)
void gemm_tf32_kernel(const float* __restrict__ A,   // [M, K] row-major
                      const float* __restrict__ b1,
                      const float* __restrict__ b2,
                      const float* __restrict__ Vv)
{
    extern __shared__ float smem[];

    constexpr int K = (MODE == 0) ? UU : EE;
    constexpr int nt_k = K >> 5;
    const float* __restrict__ Bm = (MODE == 0) ? g_w2r : g_w1r;

    const int tid = threadIdx.x;
    const int m0 = blockIdx.x * BM;
    const int n0 = blockIdx.y * BN;

    if (MODE == 0) {
        // zero score buffer (must happen every graph replay)
        int flat = (blockIdx.y * gridDim.x + blockIdx.x) * THREADS + tid;
        int tot  = gridDim.x * gridDim.y * THREADS;
        for (int i = flat; i < NB * LL; i += tot) g_score[i] = 0.f;
    }

    const int lane = tid & 31, warp = tid >> 5;
    const int gid = lane >> 2, tig = lane & 3;
    const int wm = warp & 3, wn = warp >> 2;  // warp grid 4 (M) x 2 (N)
    const int mw = wm * 32, nw = wn * 64;

    float acc[2][8][4];
    #pragma unroll
    for (int i = 0; i < 2; i++)
        #pragma unroll
        for (int j = 0; j < 8; j++)
            #pragma unroll
            for (int k = 0; k < 4; k++) acc[i][j][k] = 0.f;

    // cooperative-load indices (16B granules)
    const int a_c4 = tid & 7;    // float4 column within BK=32
    const int a_r  = tid >> 3;   // row 0..31, step 32 (x4)
    const int b_c4 = tid & 31;   // float4 column within BN=128
    const int b_r  = tid >> 5;   // row 0..7, step 8 (x4)

    unsigned aDst[STAGES], bDst[STAGES];
    #pragma unroll
    for (int s = 0; s < STAGES; s++) {
        aDst[s] = smem_u32(smem + s * STAGE_FLOATS + a_r * AS_STRIDE + a_c4 * 4);
        bDst[s] = smem_u32(smem + s * STAGE_FLOATS + AS_FLOATS + b_r * BS_STRIDE + b_c4 * 4);
    }

    const float* Abase = A + (size_t)(m0 + a_r) * K + a_c4 * 4;
    const float* Bbase = Bm + (size_t)b_r * 512 + n0 + b_c4 * 4;

    auto issue_stage = [&](int kt, int s) {
        const float* Ap = Abase + kt * BK;
        #pragma unroll
        for (int i = 0; i < 4; i++)
            cp_async16(aDst[s] + i * 32 * AS_STRIDE * 4, Ap + (size_t)(32 * i) * K);
        const float* Bp = Bbase + (size_t)(kt * BK) * 512;
        #pragma unroll
        for (int i = 0; i < 4; i++)
            cp_async16(bDst[s] + i * 8 * BS_STRIDE * 4, Bp + (size_t)(8 * i) * 512);
        asm volatile("cp.async.commit_group;\n");
    };

    issue_stage(0, 0);

    for (int kt = 0; kt < nt_k; kt++) {
        const int sc = kt & 1;
        // refill the other buffer (previous iteration's trailing __syncthreads
        // guarantees everyone finished reading it)
        if (kt + 1 < nt_k)
            issue_stage(kt + 1, sc ^ 1);
        else
            asm volatile("cp.async.commit_group;\n");   // keep group count uniform

        asm volatile("cp.async.wait_group 1;\n");       // stage kt resident
        __syncthreads();

        const float* Asp = smem + sc * STAGE_FLOATS;
        const float* Bsp = Asp + AS_FLOATS;

        #pragma unroll
        for (int kk = 0; kk < 4; kk++) {
            unsigned a[2][4];
            #pragma unroll
            for (int mt = 0; mt < 2; mt++) {
                const int r = mw + mt * 16 + gid;
                a[mt][0] = f2tf32(Asp[ r      * AS_STRIDE + kk * 8 + tig]);
                a[mt][1] = f2tf32(Asp[(r + 8) * AS_STRIDE + kk * 8 + tig]);
                a[mt][2] = f2tf32(Asp[ r      * AS_STRIDE + kk * 8 + tig + 4]);
                a[mt][3] = f2tf32(Asp[(r + 8) * AS_STRIDE + kk * 8 + tig + 4]);
            }
            #pragma unroll
            for (int nt = 0; nt < 8; nt++) {
                const int c = nw + nt * 8 + gid;
                unsigned bb0 = __float_as_uint(Bsp[(kk * 8 + tig    ) * BS_STRIDE + c]);
                unsigned bb1 = __float_as_uint(Bsp[(kk * 8 + tig + 4) * BS_STRIDE + c]);
                #pragma unroll
                for (int mt = 0; mt < 2; mt++) {
                    asm volatile(
                        "mma.sync.aligned.m16n8k8.row.col.f32.tf32.tf32.f32 "
                        "{%0,%1,%2,%3}, {%4,%5,%6,%7}, {%8,%9}, {%0,%1,%2,%3};\n"
                        : "+f"(acc[mt][nt][0]), "+f"(acc[mt][nt][1]),
                          "+f"(acc[mt][nt][2]), "+f"(acc[mt][nt][3])
                        : "r"(a[mt][0]), "r"(a[mt][1]), "r"(a[mt][2]), "r"(a[mt][3]),
                          "r"(bb0), "r"(bb1));
                }
            }
        }
        __syncthreads();   // 2-stage: next iteration's cp.async reuses this buffer
    }

    // ------------------------- epilogue -------------------------
    if (MODE == 0) {
        #pragma unroll
        for (int mt = 0; mt < 2; mt++) {
            int r0 = m0 + mw + mt * 16 + gid;
            #pragma unroll
            for (int nt = 0; nt < 8; nt++) {
                int c0 = n0 + nw + nt * 8 + tig * 2;
                float bias0 = b1[c0] + b2[c0];
                float bias1 = b1[c0 + 1] + b2[c0 + 1];
                g_projh[(size_t)r0 * 512 + c0]           = acc[mt][nt][0] + bias0;
                g_projh[(size_t)r0 * 512 + c0 + 1]       = acc[mt][nt][1] + bias1;
                g_projh[(size_t)(r0 + 8) * 512 + c0]     = acc[mt][nt][2] + bias0;
                g_projh[(size_t)(r0 + 8) * 512 + c0 + 1] = acc[mt][nt][3] + bias1;
            }
        }
    } else {
        #pragma unroll
        for (int mt = 0; mt < 2; mt++) {
            int r0 = m0 + mw + mt * 16 + gid;          // rows r0 and r0+8 share batch
            int bidx = r0 >> 6;
            const float* ph = g_projh + (size_t)bidx * 512;
            float p0 = 0.f, p1 = 0.f;
            #pragma unroll
            for (int nt = 0; nt < 8; nt++) {
                int c0 = n0 + nw + nt * 8 + tig * 2;
                float v0 = Vv[c0], v1 = Vv[c0 + 1];
                float h0 = ph[c0], h1 = ph[c0 + 1];
                p0 += v0 * tanhf(acc[mt][nt][0] + h0);
                p0 += v1 * tanhf(acc[mt][nt][1] + h1);
                p1 += v0 * tanhf(acc[mt][nt][2] + h0);
                p1 += v1 * tanhf(acc[mt][nt][3] + h1);
            }
            p0 += __shfl_xor_sync(0xffffffffu, p0, 1);
            p0 += __shfl_xor_sync(0xffffffffu, p0, 2);
            p1 += __shfl_xor_sync(0xffffffffu, p1, 1);
            p1 += __shfl_xor_sync(0xffffffffu, p1, 2);
            if (tig == 0) {
                atomicAdd(&g_score[r0], p0);
                atomicAdd(&g_score[r0 + 8], p1);
            }
        }
    }
}

// ---------------------------------------------------------------------------
// Softmax over L=64 + context = sum_l w[l] * features[b,l,:]
// out layout: [0, 524288) context [2048,256]; [524288, 655360) weights [2048,64]
// ---------------------------------------------------------------------------
__global__ __launch_bounds__(256)
void softmax_ctx_kernel(const float* __restrict__ feat, float* __restrict__ out)
{
    const int b = blockIdx.x;
    const int tid = threadIdx.x;

    __shared__ float w[LL];
    __shared__ float redmax[2];
    __shared__ float redsum[2];

    float s = (tid < LL) ? g_score[b * LL + tid] : -3.0e38f;

    float m = s;
    #pragma unroll
    for (int o = 16; o > 0; o >>= 1)
        m = fmaxf(m, __shfl_xor_sync(0xffffffffu, m, o));
    if (tid == 0)  redmax[0] = m;
    if (tid == 32) redmax[1] = m;
    __syncthreads();
    const float mx = fmaxf(redmax[0], redmax[1]);

    float e = (tid < LL) ? expf(s - mx) : 0.f;
    float sum = e;
    #pragma unroll
    for (int o = 16; o > 0; o >>= 1)
        sum += __shfl_xor_sync(0xffffffffu, sum, o);
    if (tid == 0)  redsum[0] = sum;
    if (tid == 32) redsum[1] = sum;
    __syncthreads();
    const float tot = redsum[0] + redsum[1];

    if (tid < LL) {
        float wt = e / tot;
        w[tid] = wt;
        out[CTX_ELEMS + b * LL + tid] = wt;
    }
    __syncthreads();

    // context: each thread owns one embedding channel (E = 256 = blockDim)
    float acc = 0.f;
    const float* fb = feat + (size_t)b * LL * EE + tid;
    #pragma unroll 16
    for (int l = 0; l < LL; l++)
        acc = fmaf(w[l], fb[l * EE], acc);
    out[b * EE + tid] = acc;
}

// ---------------------------------------------------------------------------
extern "C" void kernel_launch(void* const* d_in, const int* in_sizes, int n_in,
                              void* d_out, int out_size)
{
    const float* features = (const float*)d_in[0];  // [2048,64,256]
    const float* hidden   = (const float*)d_in[1];  // [2048,512]
    const float* W1       = (const float*)d_in[2];  // [256,512]
    const float* b1       = (const float*)d_in[3];  // [512]
    const float* W2       = (const float*)d_in[4];  // [512,512]
    const float* b2       = (const float*)d_in[5];  // [512]
    const float* V        = (const float*)d_in[6];  // [512,1]
    // d_in[7] = bv: constant added to every score -> softmax-invariant, ignored.
    float* out = (float*)d_out;

    cudaFuncSetAttribute(gemm_tf32_kernel<0>,
                         cudaFuncAttributeMaxDynamicSharedMemorySize, SMEM_BYTES);
    cudaFuncSetAttribute(gemm_tf32_kernel<1>,
                         cudaFuncAttributeMaxDynamicSharedMemorySize, SMEM_BYTES);

    // 0) pre-round W1, W2 to tf32 (RNA) into device scratch
    round_weights_kernel<<<(EE * UU + UU * UU + 255) / 256, 256>>>(W1, W2);

    // 1) proj_h = hidden @ W2r + (b1+b2)   [also zero-inits score each replay]
    dim3 g0(NB / BM, UU / BN);       // 16 x 4
    gemm_tf32_kernel<0><<<g0, THREADS, SMEM_BYTES>>>(hidden, b1, b2, nullptr);

    // 2) fused proj_f GEMM + tanh + V-dot -> score (atomic accumulate)
    dim3 g1(MROWS / BM, UU / BN);    // 1024 x 4
    gemm_tf32_kernel<1><<<g1, THREADS, SMEM_BYTES>>>(features, nullptr, nullptr, V);

    // 3) softmax over L + context reduction; writes both outputs
    softmax_ctx_kernel<<<NB, 256>>>(features, out);
}